// round 3
// baseline (speedup 1.0000x reference)
#include <cuda_runtime.h>
#include <cfloat>
#include <cstdint>

// ---------------------------------------------------------------------------
// DeeperGCN forward on GB300.
// Pipeline per launch:
//   atom-encode -> CSR build (counting sort by dst) -> per layer:
//     [BN stats (2-stage)] -> edge online-softmax aggregation (BN+ReLU folded
//     into the gather) -> K-chunked 128x128 smem GEMM (+bias, +residual)
//   -> final BN stats -> fused pool+dot+sigmoid+blend.
// All shared memory is static and <= 48KB: no cudaFuncSetAttribute, no
// dynamic-smem opt-in anywhere in the (graph-captured) launch path.
// ---------------------------------------------------------------------------

#define NMAX 102400
#define EMAX 615000
#define GMAX 2048
#define D    128

__device__ float g_h[NMAX * D];      // node features
__device__ float g_p[NMAX * D];      // GEMM input (hin + aggr)
__device__ int   g_rowptr[NMAX + 1];
__device__ int   g_cursor[NMAX];
__device__ int   g_cnt[NMAX];
__device__ int   g_inc[NMAX];
__device__ int   g_bsums[256];
__device__ int   g_boff[256];
__device__ int   g_colsrc[EMAX];
__device__ int   g_attr[EMAX];
__device__ int   g_gcnt[GMAX];
__device__ int   g_gstart[GMAX + 1];
__device__ float g_part1[256 * D];
__device__ float g_part2[256 * D];
__device__ float g_A[D];             // folded BN scale
__device__ float g_B[D];             // folded BN shift

// ---------------- fast math (FMA-pipe only; avoids MUFU floods) ------------

// exp(x) for x <= 0 (softmax-safe). rel err ~2e-6. ~11 ALU/FMA ops, no MUFU.
__device__ __forceinline__ float fexp(float x) {
    float y = x * 1.4426950408889634f;          // log2(e)
    y = fmaxf(y, -125.0f);
    float r = y + 12582912.0f;                  // round-to-nearest-int trick
    int   n = __float_as_int(r) - 0x4B400000;   // integer part
    float f = y - (r - 12582912.0f);            // frac in [-0.5, 0.5]
    float p =            1.3333558146e-3f;
    p = fmaf(p, f, 9.6181291076e-3f);
    p = fmaf(p, f, 5.5504108665e-2f);
    p = fmaf(p, f, 2.4022650696e-1f);
    p = fmaf(p, f, 6.9314718056e-1f);
    p = fmaf(p, f, 1.0f);
    return __int_as_float(__float_as_int(p) + n * 8388608);  // * 2^n
}

// 1/x for x > 0. Magic guess + 3 Newton steps, rel err ~1e-7. No MUFU.
__device__ __forceinline__ float frcp(float x) {
    float r = __int_as_float(0x7EF311C3 - __float_as_int(x));
    r = r * (2.0f - x * r);
    r = r * (2.0f - x * r);
    r = r * (2.0f - x * r);
    return r;
}

__device__ __forceinline__ float4 bnrelu4(float4 h, float4 A, float4 B) {
    float4 o;
    o.x = fmaxf(fmaf(A.x, h.x, B.x), 0.f);
    o.y = fmaxf(fmaf(A.y, h.y, B.y), 0.f);
    o.z = fmaxf(fmaf(A.z, h.z, B.z), 0.f);
    o.w = fmaxf(fmaf(A.w, h.w, B.w), 0.f);
    return o;
}

// Online softmax update with a SINGLE exp: exp(-|z-m|) serves as either the
// rescale of the running sums (z > m) or the new term's weight (z <= m).
__device__ __forceinline__ void sm_update(float z, float msg,
                                          float& m, float& s, float& ws) {
    float d  = z - m;
    float e  = fexp(-fabsf(d));
    bool  up = d > 0.f;
    float sc = up ? e : 1.f;
    float ee = up ? 1.f : e;
    s  = fmaf(s, sc, ee);
    ws = fmaf(ws, sc, ee * msg);
    m  = fmaxf(m, z);
}

// ------------------------------- kernels -----------------------------------

__global__ void k_atom(const int* __restrict__ x, const float* __restrict__ emb,
                       int N) {
    int n = blockIdx.x;
    if (n >= N) return;
    __shared__ int xi[9];
    if (threadIdx.x < 9) xi[threadIdx.x] = x[n * 9 + threadIdx.x];
    __syncthreads();
    float s = 0.f;
#pragma unroll
    for (int f = 0; f < 9; f++) s += emb[(f * 64 + xi[f]) * D + threadIdx.x];
    g_h[n * D + threadIdx.x] = s;
}

__global__ void k_zero(int N, int G) {
    int i = blockIdx.x * 256 + threadIdx.x;
    if (i < N) g_cnt[i] = 0;
    if (i < G) g_gcnt[i] = 0;
}

__global__ void k_hist(const int* __restrict__ dst, int E) {
    int i = blockIdx.x * 256 + threadIdx.x;
    if (i < E) atomicAdd(&g_cnt[dst[i]], 1);
}

__global__ void k_ghist(const int* __restrict__ batch, int N) {
    int i = blockIdx.x * 256 + threadIdx.x;
    if (i < N) atomicAdd(&g_gcnt[batch[i]], 1);
}

__global__ void k_scan_part(int N) {
    __shared__ int sh[512];
    int t = threadIdx.x;
    int i = blockIdx.x * 512 + t;
    sh[t] = (i < N) ? g_cnt[i] : 0;
    __syncthreads();
    for (int off = 1; off < 512; off <<= 1) {
        int u = (t >= off) ? sh[t - off] : 0;
        __syncthreads();
        sh[t] += u;
        __syncthreads();
    }
    if (i < N) g_inc[i] = sh[t];
    if (t == 511) g_bsums[blockIdx.x] = sh[511];
}

__global__ void k_scan_top(int nb) {
    if (threadIdx.x == 0 && blockIdx.x == 0) {
        int run = 0;
        for (int b = 0; b < nb; b++) { g_boff[b] = run; run += g_bsums[b]; }
    }
}

__global__ void k_finalize(int N, int E) {
    int i = blockIdx.x * 256 + threadIdx.x;
    if (i < N) {
        int rp = g_inc[i] - g_cnt[i] + g_boff[i >> 9];
        g_rowptr[i] = rp;
        g_cursor[i] = rp;
    }
    if (i == 0) g_rowptr[N] = E;
}

__global__ void k_gscan(int G) {
    if (threadIdx.x == 0 && blockIdx.x == 0) {
        int run = 0;
        for (int g = 0; g < G; g++) { g_gstart[g] = run; run += g_gcnt[g]; }
        g_gstart[G] = run;
    }
}

__global__ void k_scatter(const int* __restrict__ src,
                          const int* __restrict__ dst,
                          const int* __restrict__ ea, int E) {
    int i = blockIdx.x * 256 + threadIdx.x;
    if (i >= E) return;
    int d   = dst[i];
    int pos = atomicAdd(&g_cursor[d], 1);
    g_colsrc[pos] = src[i];
    g_attr[pos]   = ea[3 * i] | (ea[3 * i + 1] << 8) | (ea[3 * i + 2] << 16);
}

__global__ void k_bn_part(int N) {
    int t  = threadIdx.x;
    int r0 = blockIdx.x * 512;
    int re = min(r0 + 512, N);
    float s1 = 0.f, s2 = 0.f;
    for (int r = r0; r < re; r++) {
        float v = g_h[r * D + t];
        s1 += v;
        s2 = fmaf(v, v, s2);
    }
    g_part1[blockIdx.x * D + t] = s1;
    g_part2[blockIdx.x * D + t] = s2;
}

__global__ void k_bn_final(int nb, int N, const float* __restrict__ gamma,
                           const float* __restrict__ beta) {
    int t = threadIdx.x;
    float s1 = 0.f, s2 = 0.f;
    for (int b = 0; b < nb; b++) {
        s1 += g_part1[b * D + t];
        s2 += g_part2[b * D + t];
    }
    float invN = 1.0f / (float)N;
    float mu   = s1 * invN;
    float var  = fmaxf(s2 * invN - mu * mu, 0.f);
    float inv  = rsqrtf(var + 1e-5f);
    float A    = gamma[t] * inv;
    g_A[t] = A;
    g_B[t] = fmaf(-mu, A, beta[t]);
}

// One warp per destination node. Online softmax over its incoming edges,
// BN+ReLU folded into every h read. Writes p = hin + aggr.
__global__ __launch_bounds__(256) void k_edge(const float* __restrict__ bond,
                                              const float* __restrict__ ts_l,
                                              int N, int bnflag) {
    __shared__ float4 s_bond[768];   // bond_emb [3][8][128] as float4
    __shared__ float4 sA[32], sB[32];
    int t = threadIdx.x;
    const float4* bond4 = (const float4*)bond;
    for (int i = t; i < 768; i += 256) s_bond[i] = bond4[i];
    if (t < 32) {
        sA[t] = ((const float4*)g_A)[t];
        sB[t] = ((const float4*)g_B)[t];
    }
    __syncthreads();

    int n = blockIdx.x * 8 + (t >> 5);
    if (n >= N) return;
    int lane = t & 31;

    float  tsc = __ldg(ts_l);
    float4 A = sA[lane], B = sB[lane];

    const float4* H4 = (const float4*)g_h;
    float4 hn = H4[n * 32 + lane];
    if (bnflag) hn = bnrelu4(hn, A, B);

    int beg = g_rowptr[n], end = g_rowptr[n + 1];
    float4 m  = make_float4(-FLT_MAX, -FLT_MAX, -FLT_MAX, -FLT_MAX);
    float4 s  = make_float4(0.f, 0.f, 0.f, 0.f);
    float4 ws = make_float4(0.f, 0.f, 0.f, 0.f);

    for (int e = beg; e < end; e++) {
        int src = g_colsrc[e];
        int pa  = g_attr[e];
        float4 hs = H4[src * 32 + lane];
        if (bnflag) hs = bnrelu4(hs, A, B);
        float4 b0 = s_bond[(pa & 0xFF) * 32 + lane];
        float4 b1 = s_bond[(8 + ((pa >> 8) & 0xFF)) * 32 + lane];
        float4 b2 = s_bond[(16 + ((pa >> 16) & 0xFF)) * 32 + lane];
        float4 msg;
        msg.x = fmaxf(hs.x + b0.x + b1.x + b2.x, 0.f) + 1e-7f;
        msg.y = fmaxf(hs.y + b0.y + b1.y + b2.y, 0.f) + 1e-7f;
        msg.z = fmaxf(hs.z + b0.z + b1.z + b2.z, 0.f) + 1e-7f;
        msg.w = fmaxf(hs.w + b0.w + b1.w + b2.w, 0.f) + 1e-7f;
        sm_update(tsc * msg.x, msg.x, m.x, s.x, ws.x);
        sm_update(tsc * msg.y, msg.y, m.y, s.y, ws.y);
        sm_update(tsc * msg.z, msg.z, m.z, s.z, ws.z);
        sm_update(tsc * msg.w, msg.w, m.w, s.w, ws.w);
    }

    float4 o;
    o.x = fmaf(ws.x, frcp(s.x + 1e-16f), hn.x);
    o.y = fmaf(ws.y, frcp(s.y + 1e-16f), hn.y);
    o.z = fmaf(ws.z, frcp(s.z + 1e-16f), hn.z);
    o.w = fmaf(ws.w, frcp(s.w + 1e-16f), hn.w);
    ((float4*)g_p)[n * 32 + lane] = o;
}

// h = p @ W + bias (+ h if addRes). 128x128 output tile per block, K chunked
// by 32 so static smem stays under 48KB (sW 16KB + sP ~18.4KB). 8x8 microtile.
__global__ __launch_bounds__(256) void k_gemm(const float* __restrict__ W,
                                              const float* __restrict__ bias,
                                              int N, int addRes) {
    __shared__ float sW[32][128];    // W[k][c] chunk
    __shared__ float sP[128][36];    // P rows x 32 K-cols, stride 36 (16B-aligned)

    int t    = threadIdx.x;
    int row0 = blockIdx.x * 128;
    int tx = t & 15, ty = t >> 4;
    int c0 = tx * 8, r0 = ty * 8;

    float acc[8][8];
#pragma unroll
    for (int i = 0; i < 8; i++)
#pragma unroll
        for (int j = 0; j < 8; j++) acc[i][j] = 0.f;

    const float4* P4 = (const float4*)g_p;

    for (int kc = 0; kc < 128; kc += 32) {
        // W chunk: rows kc..kc+31, all 128 cols = 1024 float4
        const float4* W4 = (const float4*)(W + kc * 128);
        for (int i = t; i < 1024; i += 256)
            ((float4*)&sW[0][0])[i] = W4[i];
        // P chunk: 128 rows x 32 cols = 1024 float4 (8 per row)
        for (int i = t; i < 1024; i += 256) {
            int r = i >> 3, q = i & 7;
            int gr = row0 + r;
            if (gr >= N) gr = N - 1;
            float4 v = P4[gr * 32 + (kc >> 2) + q];
            *(float4*)&sP[r][q * 4] = v;
        }
        __syncthreads();

#pragma unroll
        for (int k = 0; k < 32; k++) {
            float a[8];
#pragma unroll
            for (int i = 0; i < 8; i++) a[i] = sP[r0 + i][k];
            float4 bb0 = *(float4*)&sW[k][c0];
            float4 bb1 = *(float4*)&sW[k][c0 + 4];
            float b[8] = {bb0.x, bb0.y, bb0.z, bb0.w,
                          bb1.x, bb1.y, bb1.z, bb1.w};
#pragma unroll
            for (int i = 0; i < 8; i++)
#pragma unroll
                for (int j = 0; j < 8; j++)
                    acc[i][j] = fmaf(a[i], b[j], acc[i][j]);
        }
        __syncthreads();
    }

    float4 bi0 = *(const float4*)(bias + c0);
    float4 bi1 = *(const float4*)(bias + c0 + 4);

#pragma unroll
    for (int i = 0; i < 8; i++) {
        int gr = row0 + r0 + i;
        if (gr >= N) continue;
        float* Hr = g_h + gr * 128 + c0;
        float4 o0, o1;
        o0.x = acc[i][0] + bi0.x; o0.y = acc[i][1] + bi0.y;
        o0.z = acc[i][2] + bi0.z; o0.w = acc[i][3] + bi0.w;
        o1.x = acc[i][4] + bi1.x; o1.y = acc[i][5] + bi1.y;
        o1.z = acc[i][6] + bi1.z; o1.w = acc[i][7] + bi1.w;
        if (addRes) {
            float4 h0 = *(float4*)&Hr[0];
            float4 h1 = *(float4*)&Hr[4];
            o0.x += h0.x; o0.y += h0.y; o0.z += h0.z; o0.w += h0.w;
            o1.x += h1.x; o1.y += h1.y; o1.z += h1.z; o1.w += h1.w;
        }
        *(float4*)&Hr[0] = o0;
        *(float4*)&Hr[4] = o1;
    }
}

// Fused: final BN+ReLU (A,B in g_A/g_B), mean pool, dot with final_w,
// sigmoid, blend with rf_pred.
__global__ void k_pool(const float* __restrict__ fw, const float* __restrict__ fb,
                       const float* __restrict__ betap, const float* __restrict__ rf,
                       float* __restrict__ out, int G) {
    int g = blockIdx.x;
    if (g >= G) return;
    int t   = threadIdx.x;
    int beg = g_gstart[g], end = g_gstart[g + 1];
    float A = g_A[t], B = g_B[t];
    float ssum = 0.f;
    for (int r = beg; r < end; r++) {
        float v = g_h[r * D + t];
        ssum += fmaxf(fmaf(A, v, B), 0.f);
    }
    int   cnt = end - beg;
    float ic  = (cnt > 0) ? 1.0f / (float)cnt : 1.0f;
    float val = ssum * ic * fw[t];
    __shared__ float red[D];
    red[t] = val;
    __syncthreads();
    for (int off = 64; off > 0; off >>= 1) {
        if (t < off) red[t] += red[t + off];
        __syncthreads();
    }
    if (t == 0) {
        float pred = red[0] + fb[0];
        float b    = betap[0];
        float sg   = 1.0f / (1.0f + expf(-pred));
        out[g] = (1.0f - b) * sg + b * rf[g];
    }
}

// ------------------------------- host --------------------------------------

extern "C" void kernel_launch(void* const* d_in, const int* in_sizes, int n_in,
                              void* d_out, int out_size) {
    const int*   x     = (const int*)d_in[0];
    const int*   ei    = (const int*)d_in[1];
    const int*   ea    = (const int*)d_in[2];
    const int*   batch = (const int*)d_in[3];
    const float* rf    = (const float*)d_in[4];
    const float* atom  = (const float*)d_in[5];
    const float* bond  = (const float*)d_in[6];
    const float* cw    = (const float*)d_in[7];
    const float* cb    = (const float*)d_in[8];
    const float* ts    = (const float*)d_in[9];
    const float* gam   = (const float*)d_in[10];
    const float* bbe   = (const float*)d_in[11];
    const float* fw    = (const float*)d_in[12];
    const float* fb    = (const float*)d_in[13];
    const float* beta  = (const float*)d_in[14];
    float*       out   = (float*)d_out;

    int N = in_sizes[0] / 9;
    int E = in_sizes[1] / 2;
    int G = in_sizes[4];
    int L = in_sizes[9];
    const int* src = ei;
    const int* dst = ei + E;

    int nb  = (N + 511) / 512;
    int NG  = (N > G) ? N : G;

    k_atom<<<N, 128>>>(x, atom, N);
    k_zero<<<(NG + 255) / 256, 256>>>(N, G);
    k_hist<<<(E + 255) / 256, 256>>>(dst, E);
    k_ghist<<<(N + 255) / 256, 256>>>(batch, N);
    k_scan_part<<<nb, 512>>>(N);
    k_scan_top<<<1, 1>>>(nb);
    k_finalize<<<(N + 255) / 256, 256>>>(N, E);
    k_gscan<<<1, 1>>>(G);
    k_scatter<<<(E + 255) / 256, 256>>>(src, dst, ea, E);

    int edgeGrid = (N + 7) / 8;
    int gemmGrid = (N + 127) / 128;
    for (int l = 0; l < L; l++) {
        if (l > 0) {
            k_bn_part<<<nb, 128>>>(N);
            k_bn_final<<<1, 128>>>(nb, N, gam + (l - 1) * D, bbe + (l - 1) * D);
        }
        k_edge<<<edgeGrid, 256>>>(bond, ts + l, N, (l > 0) ? 1 : 0);
        k_gemm<<<gemmGrid, 256>>>(cw + l * D * D, cb + l * D, N,
                                  (l > 0) ? 1 : 0);
    }
    k_bn_part<<<nb, 128>>>(N);
    k_bn_final<<<1, 128>>>(nb, N, gam + (L - 1) * D, bbe + (L - 1) * D);
    k_pool<<<G, 128>>>(fw, fb, beta, rf, out, G);
}

// round 7
// speedup vs baseline: 1.1646x; 1.1646x over previous
#include <cuda_runtime.h>
#include <cfloat>
#include <cstdint>

// ---------------------------------------------------------------------------
// DeeperGCN forward on GB300, round 3 design (resubmitted; broker timeouts).
//  - k_edge: max-free online softmax (shift-invariant; z bounded), software
//    pipelined gathers, packed int2 edge records.
//  - BN stats fused into GEMM epilogue (no separate pass over h).
//  - gstart via binary search on sorted batch (no atomics, no serial scan).
// ---------------------------------------------------------------------------

#define NMAX 102400
#define EMAX 615000
#define D    128

__device__ float g_h[NMAX * D];      // node features
__device__ float g_p[NMAX * D];      // GEMM input (hin + aggr)
__device__ int   g_rowptr[NMAX + 1];
__device__ int   g_cursor[NMAX];
__device__ int   g_cnt[NMAX];
__device__ int   g_inc[NMAX];
__device__ int   g_bsums[256];
__device__ int   g_boff[256];
__device__ int2  g_edge[EMAX];       // {src, packed attr}
__device__ int   g_gstart[2049];
__device__ float g_s1[8 * D];        // per-gemm-layer BN sums
__device__ float g_s2[8 * D];        // per-gemm-layer BN sumsq
__device__ float g_A[D];             // folded BN scale
__device__ float g_B[D];             // folded BN shift

// ---------------- fast math (FMA-pipe only; avoids MUFU floods) ------------

// exp(x), |x| modest (softmax logits). rel err ~2e-6. FMA/ALU only, no MUFU.
__device__ __forceinline__ float fexp(float x) {
    float y = x * 1.4426950408889634f;          // log2(e)
    y = fmaxf(fminf(y, 125.0f), -125.0f);
    float r = y + 12582912.0f;                  // round-to-nearest-int trick
    int   n = __float_as_int(r) - 0x4B400000;   // integer part
    float f = y - (r - 12582912.0f);            // frac in [-0.5, 0.5]
    float p =            1.3333558146e-3f;
    p = fmaf(p, f, 9.6181291076e-3f);
    p = fmaf(p, f, 5.5504108665e-2f);
    p = fmaf(p, f, 2.4022650696e-1f);
    p = fmaf(p, f, 6.9314718056e-1f);
    p = fmaf(p, f, 1.0f);
    return __int_as_float(__float_as_int(p) + n * 8388608);  // * 2^n
}

// 1/x for x > 0. Magic guess + 3 Newton steps, rel err ~1e-7. No MUFU.
__device__ __forceinline__ float frcp(float x) {
    float r = __int_as_float(0x7EF311C3 - __float_as_int(x));
    r = r * (2.0f - x * r);
    r = r * (2.0f - x * r);
    r = r * (2.0f - x * r);
    return r;
}

__device__ __forceinline__ float4 bnrelu4(float4 h, float4 A, float4 B) {
    float4 o;
    o.x = fmaxf(fmaf(A.x, h.x, B.x), 0.f);
    o.y = fmaxf(fmaf(A.y, h.y, B.y), 0.f);
    o.z = fmaxf(fmaf(A.z, h.z, B.z), 0.f);
    o.w = fmaxf(fmaf(A.w, h.w, B.w), 0.f);
    return o;
}

// ------------------------------- kernels -----------------------------------

__global__ void k_atom(const int* __restrict__ x, const float* __restrict__ emb,
                       int N) {
    int t  = threadIdx.x;
    int n  = blockIdx.x * 2 + (t >> 7);
    int c  = t & 127;
    __shared__ int xi[2][9];
    if (t < 18) xi[t / 9][t % 9] = (blockIdx.x * 2 + t / 9 < N)
                                     ? x[(blockIdx.x * 2 + t / 9) * 9 + t % 9] : 0;
    __syncthreads();
    if (n >= N) return;
    float s = 0.f;
#pragma unroll
    for (int f = 0; f < 9; f++) s += emb[(f * 64 + xi[t >> 7][f]) * D + c];
    g_h[n * D + c] = s;
}

__global__ void k_zero(int N) {
    int i = blockIdx.x * 256 + threadIdx.x;
    if (i < N) g_cnt[i] = 0;
    if (i < 8 * D) { g_s1[i] = 0.f; g_s2[i] = 0.f; }
}

__global__ void k_hist(const int* __restrict__ dst, int E) {
    int i = blockIdx.x * 256 + threadIdx.x;
    if (i < E) atomicAdd(&g_cnt[dst[i]], 1);
}

// gstart[g] = first index i in sorted batch with batch[i] >= g.
__global__ void k_gstart(const int* __restrict__ batch, int N, int G) {
    int g = blockIdx.x * 256 + threadIdx.x;
    if (g > G) return;
    int lo = 0, hi = N;
    while (lo < hi) {
        int mid = (lo + hi) >> 1;
        if (batch[mid] < g) lo = mid + 1; else hi = mid;
    }
    g_gstart[g] = lo;
}

__global__ void k_scan_part(int N) {
    __shared__ int sh[512];
    int t = threadIdx.x;
    int i = blockIdx.x * 512 + t;
    sh[t] = (i < N) ? g_cnt[i] : 0;
    __syncthreads();
    for (int off = 1; off < 512; off <<= 1) {
        int u = (t >= off) ? sh[t - off] : 0;
        __syncthreads();
        sh[t] += u;
        __syncthreads();
    }
    if (i < N) g_inc[i] = sh[t];
    if (t == 511) g_bsums[blockIdx.x] = sh[511];
}

__global__ void k_scan_top(int nb) {
    if (threadIdx.x == 0 && blockIdx.x == 0) {
        int run = 0;
        for (int b = 0; b < nb; b++) { g_boff[b] = run; run += g_bsums[b]; }
    }
}

__global__ void k_finalize(int N, int E) {
    int i = blockIdx.x * 256 + threadIdx.x;
    if (i < N) {
        int rp = g_inc[i] - g_cnt[i] + g_boff[i >> 9];
        g_rowptr[i] = rp;
        g_cursor[i] = rp;
    }
    if (i == 0) g_rowptr[N] = E;
}

__global__ void k_scatter(const int* __restrict__ src,
                          const int* __restrict__ dst,
                          const int* __restrict__ ea, int E) {
    int i = blockIdx.x * 256 + threadIdx.x;
    if (i >= E) return;
    int d   = dst[i];
    int pos = atomicAdd(&g_cursor[d], 1);
    g_edge[pos] = make_int2(src[i],
                            ea[3 * i] | (ea[3 * i + 1] << 8) | (ea[3 * i + 2] << 16));
}

__global__ void k_bn_final(int l, int N, const float* __restrict__ gamma,
                           const float* __restrict__ beta) {
    int t = threadIdx.x;
    float invN = 1.0f / (float)N;
    float mu   = g_s1[l * D + t] * invN;
    float var  = fmaxf(g_s2[l * D + t] * invN - mu * mu, 0.f);
    float inv  = rsqrtf(var + 1e-5f);
    float A    = gamma[t] * inv;
    g_A[t] = A;
    g_B[t] = fmaf(-mu, A, beta[t]);
}

// One warp per destination node. Max-free softmax over its incoming edges,
// BN+ReLU folded into every h read. Writes p = hin + aggr.
__global__ __launch_bounds__(256) void k_edge(const float* __restrict__ bond,
                                              const float* __restrict__ ts_l,
                                              int N, int bnflag) {
    __shared__ float4 s_bond[768];   // bond_emb [3][8][128] as float4
    __shared__ float4 sA[32], sB[32];
    int t = threadIdx.x;
    const float4* bond4 = (const float4*)bond;
    for (int i = t; i < 768; i += 256) s_bond[i] = bond4[i];
    if (t < 32) {
        sA[t] = ((const float4*)g_A)[t];
        sB[t] = ((const float4*)g_B)[t];
    }
    __syncthreads();

    int n = blockIdx.x * 8 + (t >> 5);
    if (n >= N) return;
    int lane = t & 31;

    float  tsc = __ldg(ts_l);
    float4 A = sA[lane], B = sB[lane];

    const float4* H4 = (const float4*)g_h;
    float4 hn = H4[n * 32 + lane];
    if (bnflag) hn = bnrelu4(hn, A, B);

    int beg = g_rowptr[n], end = g_rowptr[n + 1];
    float4 s  = make_float4(0.f, 0.f, 0.f, 0.f);
    float4 ws = make_float4(0.f, 0.f, 0.f, 0.f);

    if (beg < end) {
        int2   ed = g_edge[beg];
        float4 hs = H4[ed.x * 32 + lane];
        for (int e = beg; e < end; e++) {
            int2 edn = ed;
            float4 hsn = hs;
            if (e + 1 < end) {                      // prefetch next edge
                edn = g_edge[e + 1];
                hsn = H4[edn.x * 32 + lane];
            }
            int pa = ed.y;
            float4 h4 = bnflag ? bnrelu4(hs, A, B) : hs;
            float4 b0 = s_bond[(pa & 0xFF) * 32 + lane];
            float4 b1 = s_bond[(8 + ((pa >> 8) & 0xFF)) * 32 + lane];
            float4 b2 = s_bond[(16 + ((pa >> 16) & 0xFF)) * 32 + lane];
            float4 msg;
            msg.x = fmaxf(h4.x + b0.x + b1.x + b2.x, 0.f) + 1e-7f;
            msg.y = fmaxf(h4.y + b0.y + b1.y + b2.y, 0.f) + 1e-7f;
            msg.z = fmaxf(h4.z + b0.z + b1.z + b2.z, 0.f) + 1e-7f;
            msg.w = fmaxf(h4.w + b0.w + b1.w + b2.w, 0.f) + 1e-7f;
            float e0 = fexp(tsc * msg.x);
            float e1 = fexp(tsc * msg.y);
            float e2 = fexp(tsc * msg.z);
            float e3 = fexp(tsc * msg.w);
            s.x += e0; ws.x = fmaf(e0, msg.x, ws.x);
            s.y += e1; ws.y = fmaf(e1, msg.y, ws.y);
            s.z += e2; ws.z = fmaf(e2, msg.z, ws.z);
            s.w += e3; ws.w = fmaf(e3, msg.w, ws.w);
            ed = edn; hs = hsn;
        }
    }

    float4 o;
    o.x = fmaf(ws.x, frcp(s.x + 1e-16f), hn.x);
    o.y = fmaf(ws.y, frcp(s.y + 1e-16f), hn.y);
    o.z = fmaf(ws.z, frcp(s.z + 1e-16f), hn.z);
    o.w = fmaf(ws.w, frcp(s.w + 1e-16f), hn.w);
    ((float4*)g_p)[n * 32 + lane] = o;
}

// h = p @ W + bias (+ h if addRes). 128x128 output tile per block, K chunked
// by 32 (static smem < 48KB). 8x8 microtile. Epilogue accumulates BN stats
// (sum, sumsq) of the freshly written h into g_s1/g_s2[layer].
__global__ __launch_bounds__(256) void k_gemm(const float* __restrict__ W,
                                              const float* __restrict__ bias,
                                              int N, int addRes, int layer) {
    __shared__ float sW[32][128];    // W[k][c] chunk; reused as reduction space
    __shared__ float sP[128][36];    // P rows x 32 K-cols, stride 36

    int t    = threadIdx.x;
    int row0 = blockIdx.x * 128;
    int tx = t & 15, ty = t >> 4;
    int c0 = tx * 8, r0 = ty * 8;

    float acc[8][8];
#pragma unroll
    for (int i = 0; i < 8; i++)
#pragma unroll
        for (int j = 0; j < 8; j++) acc[i][j] = 0.f;

    const float4* P4 = (const float4*)g_p;

    for (int kc = 0; kc < 128; kc += 32) {
        const float4* W4 = (const float4*)(W + kc * 128);
        for (int i = t; i < 1024; i += 256)
            ((float4*)&sW[0][0])[i] = W4[i];
        for (int i = t; i < 1024; i += 256) {
            int r = i >> 3, q = i & 7;
            int gr = row0 + r;
            if (gr >= N) gr = N - 1;
            float4 v = P4[gr * 32 + (kc >> 2) + q];
            *(float4*)&sP[r][q * 4] = v;
        }
        __syncthreads();

#pragma unroll
        for (int k = 0; k < 32; k++) {
            float a[8];
#pragma unroll
            for (int i = 0; i < 8; i++) a[i] = sP[r0 + i][k];
            float4 bb0 = *(float4*)&sW[k][c0];
            float4 bb1 = *(float4*)&sW[k][c0 + 4];
            float b[8] = {bb0.x, bb0.y, bb0.z, bb0.w,
                          bb1.x, bb1.y, bb1.z, bb1.w};
#pragma unroll
            for (int i = 0; i < 8; i++)
#pragma unroll
                for (int j = 0; j < 8; j++)
                    acc[i][j] = fmaf(a[i], b[j], acc[i][j]);
        }
        __syncthreads();
    }

    float4 bi0 = *(const float4*)(bias + c0);
    float4 bi1 = *(const float4*)(bias + c0 + 4);

    float s1[8], s2[8];
#pragma unroll
    for (int j = 0; j < 8; j++) { s1[j] = 0.f; s2[j] = 0.f; }

#pragma unroll
    for (int i = 0; i < 8; i++) {
        int gr = row0 + r0 + i;
        if (gr >= N) continue;
        float* Hr = g_h + gr * 128 + c0;
        float o[8];
        o[0] = acc[i][0] + bi0.x; o[1] = acc[i][1] + bi0.y;
        o[2] = acc[i][2] + bi0.z; o[3] = acc[i][3] + bi0.w;
        o[4] = acc[i][4] + bi1.x; o[5] = acc[i][5] + bi1.y;
        o[6] = acc[i][6] + bi1.z; o[7] = acc[i][7] + bi1.w;
        if (addRes) {
            float4 h0 = *(float4*)&Hr[0];
            float4 h1 = *(float4*)&Hr[4];
            o[0] += h0.x; o[1] += h0.y; o[2] += h0.z; o[3] += h0.w;
            o[4] += h1.x; o[5] += h1.y; o[6] += h1.z; o[7] += h1.w;
        }
#pragma unroll
        for (int j = 0; j < 8; j++) {
            s1[j] += o[j];
            s2[j] = fmaf(o[j], o[j], s2[j]);
        }
        *(float4*)&Hr[0] = make_float4(o[0], o[1], o[2], o[3]);
        *(float4*)&Hr[4] = make_float4(o[4], o[5], o[6], o[7]);
    }

    // Block-reduce BN partials in reused sW space: [16 ty][128 cols] x2.
    float* redS1 = &sW[0][0];
    float* redS2 = &sW[0][0] + 2048;
#pragma unroll
    for (int j = 0; j < 8; j++) {
        redS1[ty * 128 + c0 + j] = s1[j];
        redS2[ty * 128 + c0 + j] = s2[j];
    }
    __syncthreads();
    if (t < 128) {
        float a1 = 0.f, a2 = 0.f;
#pragma unroll
        for (int y = 0; y < 16; y++) {
            a1 += redS1[y * 128 + t];
            a2 += redS2[y * 128 + t];
        }
        atomicAdd(&g_s1[layer * D + t], a1);
        atomicAdd(&g_s2[layer * D + t], a2);
    }
}

// Fused: final BN+ReLU (A,B in g_A/g_B), mean pool, dot with final_w,
// sigmoid, blend with rf_pred.
__global__ void k_pool(const float* __restrict__ fw, const float* __restrict__ fb,
                       const float* __restrict__ betap, const float* __restrict__ rf,
                       float* __restrict__ out, int G) {
    int g = blockIdx.x;
    if (g >= G) return;
    int t   = threadIdx.x;
    int beg = g_gstart[g], end = g_gstart[g + 1];
    float A = g_A[t], B = g_B[t];
    float ssum = 0.f;
    for (int r = beg; r < end; r++) {
        float v = g_h[r * D + t];
        ssum += fmaxf(fmaf(A, v, B), 0.f);
    }
    int   cnt = end - beg;
    float ic  = (cnt > 0) ? 1.0f / (float)cnt : 1.0f;
    float val = ssum * ic * fw[t];
    __shared__ float red[D];
    red[t] = val;
    __syncthreads();
    for (int off = 64; off > 0; off >>= 1) {
        if (t < off) red[t] += red[t + off];
        __syncthreads();
    }
    if (t == 0) {
        float pred = red[0] + fb[0];
        float b    = betap[0];
        float sg   = 1.0f / (1.0f + expf(-pred));
        out[g] = (1.0f - b) * sg + b * rf[g];
    }
}

// ------------------------------- host --------------------------------------

extern "C" void kernel_launch(void* const* d_in, const int* in_sizes, int n_in,
                              void* d_out, int out_size) {
    const int*   x     = (const int*)d_in[0];
    const int*   ei    = (const int*)d_in[1];
    const int*   ea    = (const int*)d_in[2];
    const int*   batch = (const int*)d_in[3];
    const float* rf    = (const float*)d_in[4];
    const float* atom  = (const float*)d_in[5];
    const float* bond  = (const float*)d_in[6];
    const float* cw    = (const float*)d_in[7];
    const float* cb    = (const float*)d_in[8];
    const float* ts    = (const float*)d_in[9];
    const float* gam   = (const float*)d_in[10];
    const float* bbe   = (const float*)d_in[11];
    const float* fw    = (const float*)d_in[12];
    const float* fb    = (const float*)d_in[13];
    const float* beta  = (const float*)d_in[14];
    float*       out   = (float*)d_out;

    int N = in_sizes[0] / 9;
    int E = in_sizes[1] / 2;
    int G = in_sizes[4];
    int L = in_sizes[9];
    const int* src = ei;
    const int* dst = ei + E;

    int nb = (N + 511) / 512;

    k_atom<<<(N + 1) / 2, 256>>>(x, atom, N);
    k_zero<<<(N + 255) / 256, 256>>>(N);
    k_hist<<<(E + 255) / 256, 256>>>(dst, E);
    k_gstart<<<(G + 256) / 256, 256>>>(batch, N, G);
    k_scan_part<<<nb, 512>>>(N);
    k_scan_top<<<1, 1>>>(nb);
    k_finalize<<<(N + 255) / 256, 256>>>(N, E);
    k_scatter<<<(E + 255) / 256, 256>>>(src, dst, ea, E);

    int edgeGrid = (N + 7) / 8;
    int gemmGrid = (N + 127) / 128;
    for (int l = 0; l < L; l++) {
        if (l > 0)
            k_bn_final<<<1, 128>>>(l - 1, N, gam + (l - 1) * D, bbe + (l - 1) * D);
        k_edge<<<edgeGrid, 256>>>(bond, ts + l, N, (l > 0) ? 1 : 0);
        k_gemm<<<gemmGrid, 256>>>(cw + l * D * D, cb + l * D, N,
                                  (l > 0) ? 1 : 0, l);
    }
    k_bn_final<<<1, 128>>>(L - 1, N, gam + (L - 1) * D, bbe + (L - 1) * D);
    k_pool<<<G, 128>>>(fw, fb, beta, rf, out, G);
}